// round 8
// baseline (speedup 1.0000x reference)
#include <cuda_runtime.h>
#include <cstdint>

// Izhikevich neuron simulation on GB300 — round 5.
// 512 CTAs x 256 threads (8 warps), each CTA owns 32 sequences.
// Roles rotated across physical warps per CTA (SMSP load balance):
//   rwid 0: compute (serial chain, SMEM->SMEM)
//   rwid 1: producer (cp.async GMEM->SMEM, double buffered)
//   rwid 2-7: store warps, 3 streams x 2 time-halves (10 STG each)

#define BATCH    32
#define NSTEPS   2000
#define NNEUR    512
#define PLANE    (NSTEPS * NNEUR)
#define NTOT     (BATCH * PLANE)
#define CHUNK    20
#define HALF     (CHUNK / 2)
#define NCHUNKS  (NSTEPS / CHUNK)        // 100
#define CHEL     (CHUNK * NNEUR)

__device__ __forceinline__ void cp_async4(uint32_t saddr, const float* __restrict__ g)
{
    asm volatile("cp.async.ca.shared.global [%0], [%1], 4;"
                 :: "r"(saddr), "l"(g) : "memory");
}
__device__ __forceinline__ void cp_commit()
{
    asm volatile("cp.async.commit_group;" ::: "memory");
}
__device__ __forceinline__ void cp_wait0()
{
    asm volatile("cp.async.wait_group 0;" ::: "memory");
}

__global__ __launch_bounds__(256, 4)
void izhikevich_kernel(const float* __restrict__ in,
                       float* __restrict__ out_s,
                       float* __restrict__ out_v,
                       float* __restrict__ out_u)
{
    __shared__ float s_in[2][CHUNK][32];
    __shared__ float s_s [2][CHUNK][32];
    __shared__ float s_v [2][CHUNK][32];
    __shared__ float s_u [2][CHUNK][32];

    const int wid  = threadIdx.x >> 5;
    const int lane = threadIdx.x & 31;
    const int rwid = (wid + (int)blockIdx.x) & 7;   // rotated role id
    const int seq  = blockIdx.x * 32 + lane;
    const int b    = seq >> 9;
    const int n    = seq & 511;
    const int base = b * PLANE + n;

    const float* __restrict__ ip = in + base;

    float v = -65.0f;
    float u = -13.0f;   // B * C

    // ---- prologue: producer fills buffer 0 ----
    if (rwid == 1) {
        #pragma unroll
        for (int j = 0; j < CHUNK; ++j)
            cp_async4((uint32_t)__cvta_generic_to_shared(&s_in[0][j][lane]),
                      ip + j * NNEUR);
        cp_commit();
        cp_wait0();
    }
    __syncthreads();

    #pragma unroll 1
    for (int k = 0; k < NCHUNKS; ++k) {
        const int p = k & 1;

        if (rwid == 0) {
            // ---- compute chunk k (serial chain; exact reference order) ----
            #pragma unroll
            for (int j = 0; j < CHUNK; ++j) {
                float i_t = s_in[p][j][lane];
                float dv = (0.04f * v * v + 5.0f * v + 140.0f - u + i_t) * 0.5f;
                float du = (0.02f * (0.2f * v - u)) * 0.5f;
                v = v + dv;
                u = u + du;
                bool  fired = (v >= 30.0f);
                float s = fired ? 1.0f : 0.0f;
                v = fired ? -65.0f : v;
                u = fired ? u + 8.0f : u;
                s_s[p][j][lane] = s;
                s_v[p][j][lane] = v;
                s_u[p][j][lane] = u;
            }
        } else if (rwid == 1) {
            // ---- producer: cp.async chunk k+1 into the other buffer ----
            if (k + 1 < NCHUNKS) {
                const float* q = ip + (k + 1) * CHEL;
                #pragma unroll
                for (int j = 0; j < CHUNK; ++j)
                    cp_async4((uint32_t)__cvta_generic_to_shared(&s_in[p ^ 1][j][lane]),
                              q + j * NNEUR);
                cp_commit();
            }
        } else if (k >= 1) {
            // ---- store warps: drain chunk k-1; stream x half ----
            const int pm     = (k - 1) & 1;
            const int r      = rwid - 2;        // 0..5
            const int stream = r >> 1;          // 0:s 1:v 2:u
            const int half   = r & 1;
            const float (*buf)[32] =
                (stream == 0) ? s_s[pm] : (stream == 1) ? s_v[pm] : s_u[pm];
            float* __restrict__ g =
                ((stream == 0) ? out_s : (stream == 1) ? out_v : out_u)
                + base + (k - 1) * CHEL + half * HALF * NNEUR;
            #pragma unroll
            for (int j = 0; j < HALF; ++j)
                __stcs(g + j * NNEUR, buf[half * HALF + j][lane]);
        }

        if (rwid == 1)
            cp_wait0();     // chunk k+1 landed (hidden behind this iter's work)
        __syncthreads();
    }

    // ---- epilogue: drain final chunk ----
    if (rwid >= 2) {
        const int pm     = (NCHUNKS - 1) & 1;
        const int r      = rwid - 2;
        const int stream = r >> 1;
        const int half   = r & 1;
        const float (*buf)[32] =
            (stream == 0) ? s_s[pm] : (stream == 1) ? s_v[pm] : s_u[pm];
        float* __restrict__ g =
            ((stream == 0) ? out_s : (stream == 1) ? out_v : out_u)
            + base + (NCHUNKS - 1) * CHEL + half * HALF * NNEUR;
        #pragma unroll
        for (int j = 0; j < HALF; ++j)
            __stcs(g + j * NNEUR, buf[half * HALF + j][lane]);
    }
}

extern "C" void kernel_launch(void* const* d_in, const int* in_sizes, int n_in,
                              void* d_out, int out_size)
{
    const float* in = (const float*)d_in[0];
    float* out      = (float*)d_out;

    izhikevich_kernel<<<512, 256>>>(in, out, out + NTOT, out + 2 * NTOT);
}

// round 9
// speedup vs baseline: 1.0031x; 1.0031x over previous
#include <cuda_runtime.h>
#include <cstdint>

// Izhikevich neuron simulation on GB300 — round 5.
// 512 CTAs x 256 threads (8 warps), each CTA owns 32 sequences.
// Roles rotated across physical warps per CTA (SMSP load balance):
//   rwid 0: compute (serial chain, SMEM->SMEM)
//   rwid 1: producer (cp.async GMEM->SMEM, double buffered)
//   rwid 2-7: store warps, 3 streams x 2 time-halves (10 STG each)

#define BATCH    32
#define NSTEPS   2000
#define NNEUR    512
#define PLANE    (NSTEPS * NNEUR)
#define NTOT     (BATCH * PLANE)
#define CHUNK    20
#define HALF     (CHUNK / 2)
#define NCHUNKS  (NSTEPS / CHUNK)        // 100
#define CHEL     (CHUNK * NNEUR)

__device__ __forceinline__ void cp_async4(uint32_t saddr, const float* __restrict__ g)
{
    asm volatile("cp.async.ca.shared.global [%0], [%1], 4;"
                 :: "r"(saddr), "l"(g) : "memory");
}
__device__ __forceinline__ void cp_commit()
{
    asm volatile("cp.async.commit_group;" ::: "memory");
}
__device__ __forceinline__ void cp_wait0()
{
    asm volatile("cp.async.wait_group 0;" ::: "memory");
}

__global__ __launch_bounds__(256, 4)
void izhikevich_kernel(const float* __restrict__ in,
                       float* __restrict__ out_s,
                       float* __restrict__ out_v,
                       float* __restrict__ out_u)
{
    __shared__ float s_in[2][CHUNK][32];
    __shared__ float s_s [2][CHUNK][32];
    __shared__ float s_v [2][CHUNK][32];
    __shared__ float s_u [2][CHUNK][32];

    const int wid  = threadIdx.x >> 5;
    const int lane = threadIdx.x & 31;
    const int rwid = (wid + (int)blockIdx.x) & 7;   // rotated role id
    const int seq  = blockIdx.x * 32 + lane;
    const int b    = seq >> 9;
    const int n    = seq & 511;
    const int base = b * PLANE + n;

    const float* __restrict__ ip = in + base;

    float v = -65.0f;
    float u = -13.0f;   // B * C

    // ---- prologue: producer fills buffer 0 ----
    if (rwid == 1) {
        #pragma unroll
        for (int j = 0; j < CHUNK; ++j)
            cp_async4((uint32_t)__cvta_generic_to_shared(&s_in[0][j][lane]),
                      ip + j * NNEUR);
        cp_commit();
        cp_wait0();
    }
    __syncthreads();

    #pragma unroll 1
    for (int k = 0; k < NCHUNKS; ++k) {
        const int p = k & 1;

        if (rwid == 0) {
            // ---- compute chunk k (serial chain; exact reference order) ----
            #pragma unroll
            for (int j = 0; j < CHUNK; ++j) {
                float i_t = s_in[p][j][lane];
                float dv = (0.04f * v * v + 5.0f * v + 140.0f - u + i_t) * 0.5f;
                float du = (0.02f * (0.2f * v - u)) * 0.5f;
                v = v + dv;
                u = u + du;
                bool  fired = (v >= 30.0f);
                float s = fired ? 1.0f : 0.0f;
                v = fired ? -65.0f : v;
                u = fired ? u + 8.0f : u;
                s_s[p][j][lane] = s;
                s_v[p][j][lane] = v;
                s_u[p][j][lane] = u;
            }
        } else if (rwid == 1) {
            // ---- producer: cp.async chunk k+1 into the other buffer ----
            if (k + 1 < NCHUNKS) {
                const float* q = ip + (k + 1) * CHEL;
                #pragma unroll
                for (int j = 0; j < CHUNK; ++j)
                    cp_async4((uint32_t)__cvta_generic_to_shared(&s_in[p ^ 1][j][lane]),
                              q + j * NNEUR);
                cp_commit();
            }
        } else if (k >= 1) {
            // ---- store warps: drain chunk k-1; stream x half ----
            const int pm     = (k - 1) & 1;
            const int r      = rwid - 2;        // 0..5
            const int stream = r >> 1;          // 0:s 1:v 2:u
            const int half   = r & 1;
            const float (*buf)[32] =
                (stream == 0) ? s_s[pm] : (stream == 1) ? s_v[pm] : s_u[pm];
            float* __restrict__ g =
                ((stream == 0) ? out_s : (stream == 1) ? out_v : out_u)
                + base + (k - 1) * CHEL + half * HALF * NNEUR;
            #pragma unroll
            for (int j = 0; j < HALF; ++j)
                __stcs(g + j * NNEUR, buf[half * HALF + j][lane]);
        }

        if (rwid == 1)
            cp_wait0();     // chunk k+1 landed (hidden behind this iter's work)
        __syncthreads();
    }

    // ---- epilogue: drain final chunk ----
    if (rwid >= 2) {
        const int pm     = (NCHUNKS - 1) & 1;
        const int r      = rwid - 2;
        const int stream = r >> 1;
        const int half   = r & 1;
        const float (*buf)[32] =
            (stream == 0) ? s_s[pm] : (stream == 1) ? s_v[pm] : s_u[pm];
        float* __restrict__ g =
            ((stream == 0) ? out_s : (stream == 1) ? out_v : out_u)
            + base + (NCHUNKS - 1) * CHEL + half * HALF * NNEUR;
        #pragma unroll
        for (int j = 0; j < HALF; ++j)
            __stcs(g + j * NNEUR, buf[half * HALF + j][lane]);
    }
}

extern "C" void kernel_launch(void* const* d_in, const int* in_sizes, int n_in,
                              void* d_out, int out_size)
{
    const float* in = (const float*)d_in[0];
    float* out      = (float*)d_out;

    izhikevich_kernel<<<512, 256>>>(in, out, out + NTOT, out + 2 * NTOT);
}

// round 10
// speedup vs baseline: 1.3339x; 1.3298x over previous
#include <cuda_runtime.h>
#include <cuda.h>
#include <cstdint>

// Izhikevich neuron simulation on GB300 — round 6: TMA-driven pipeline.
// input:  [32, 2000, 512] fp32; output: concat(s, v, u), each [32, 2000, 512].
//
// 512 CTAs x 32 threads. Each CTA owns 32 consecutive neurons of one batch.
// TMA (cp.async.bulk.tensor.3d) moves all data:
//   - input: 6-deep SMEM ring, lane0 issues loads, mbarrier per slot
//   - compute: all 32 lanes, serial 2000-step chain, SMEM -> SMEM
//   - output: 3-deep SMEM ring x 3 streams, lane0 issues TMA stores,
//             bulk_group wait guards slot reuse
// No LDG/STG in the hot path; the warp only pays compute + a few TMA issues.

#define BATCH    32
#define NSTEPS   2000
#define NNEUR    512
#define PLANE    (NSTEPS * NNEUR)
#define NTOT     (BATCH * PLANE)
#define CHUNK    25
#define NCHUNK   (NSTEPS / CHUNK)     // 80
#define IN_RING  6
#define OUT_RING 3
#define ROWB     128                  // 32 floats per row
#define CHUNKB   (CHUNK * ROWB)       // 3200 bytes per chunk per stream

// SMEM layout (bytes)
#define SM_MBAR  0                    // IN_RING * 8
#define SM_IN    128
#define SM_OUT   (SM_IN + IN_RING * CHUNKB)
#define SM_TOTAL (SM_OUT + 3 * OUT_RING * CHUNKB)   // 48128 B

// ---------------- PTX helpers ----------------
__device__ __forceinline__ uint32_t smem_u32(const void* p) {
    uint32_t a;
    asm("{ .reg .u64 t; cvta.to.shared.u64 t, %1; cvt.u32.u64 %0, t; }"
        : "=r"(a) : "l"(p));
    return a;
}
#define MBAR_INIT(addr, cnt) \
    asm volatile("mbarrier.init.shared.b64 [%0], %1;" :: "r"(addr), "r"(cnt) : "memory")
#define MBAR_EXPECT_TX(addr, bytes) \
    asm volatile("mbarrier.arrive.expect_tx.shared.b64 _, [%0], %1;" \
                 :: "r"(addr), "r"(bytes) : "memory")
#define MBAR_WAIT(addr, parity) do {                                         \
    asm volatile(                                                            \
        "{\n\t.reg .pred P;\n\t"                                             \
        "W_%=:\n\t"                                                          \
        "mbarrier.try_wait.parity.acquire.cta.shared::cta.b64 P, [%0], %1, 0x989680;\n\t" \
        "@P bra.uni D_%=;\n\t"                                               \
        "bra.uni W_%=;\n\t"                                                  \
        "D_%=:\n\t}"                                                         \
        :: "r"(addr), "r"(parity) : "memory");                               \
} while (0)
#define TMA_LOAD(smem, map, cx, cy, cz, mbar) \
    asm volatile("cp.async.bulk.tensor.3d.shared::cta.global.tile.mbarrier::complete_tx::bytes " \
                 "[%0], [%1, {%2, %3, %4}], [%5];" \
                 :: "r"(smem), "l"(map), "r"(cx), "r"(cy), "r"(cz), "r"(mbar) : "memory")
#define TMA_STORE(map, cx, cy, cz, smem) \
    asm volatile("cp.async.bulk.tensor.3d.global.shared::cta.tile.bulk_group " \
                 "[%0, {%1, %2, %3}], [%4];" \
                 :: "l"(map), "r"(cx), "r"(cy), "r"(cz), "r"(smem) : "memory")
#define TMA_COMMIT()      asm volatile("cp.async.bulk.commit_group;" ::: "memory")
#define TMA_WAIT(n)       asm volatile("cp.async.bulk.wait_group.read %0;" :: "n"(n) : "memory")
#define FENCE_ASYNC()     asm volatile("fence.proxy.async.shared::cta;" ::: "memory")

// ---------------- TMA kernel ----------------
__global__ __launch_bounds__(32)
void izh_tma_kernel(const __grid_constant__ CUtensorMap m_in,
                    const __grid_constant__ CUtensorMap m_s,
                    const __grid_constant__ CUtensorMap m_v,
                    const __grid_constant__ CUtensorMap m_u)
{
    extern __shared__ char smem[];
    const uint32_t sb   = smem_u32(smem);
    const int      lane = threadIdx.x;
    const int      bid  = blockIdx.x;
    const int      b    = bid >> 4;          // batch
    const int      n0   = (bid & 15) * 32;   // first neuron

    if (lane == 0) {
        #pragma unroll
        for (int s = 0; s < IN_RING; ++s)
            MBAR_INIT(sb + SM_MBAR + s * 8, 1);
    }
    __syncwarp();
    if (lane == 0) {
        // prologue: fill the whole input ring
        #pragma unroll
        for (int s = 0; s < IN_RING; ++s) {
            MBAR_EXPECT_TX(sb + SM_MBAR + s * 8, CHUNKB);
            TMA_LOAD(sb + SM_IN + s * CHUNKB, &m_in, n0, s * CHUNK, b,
                     sb + SM_MBAR + s * 8);
        }
    }

    float v = -65.0f;
    float u = -13.0f;   // B * C

    int slot_in = 0, phase_in = 0, slot_out = 0;

    #pragma unroll 1
    for (int k = 0; k < NCHUNK; ++k) {
        // input chunk k ready?
        MBAR_WAIT(sb + SM_MBAR + slot_in * 8, phase_in);
        // output slot free? (group from chunk k-3 retired)
        if (lane == 0) TMA_WAIT(OUT_RING - 1);
        __syncwarp();

        const float* __restrict__ pin =
            (const float*)(smem + SM_IN + slot_in * CHUNKB);
        float* __restrict__ po =
            (float*)(smem + SM_OUT + slot_out * 3 * CHUNKB);

        #pragma unroll
        for (int j = 0; j < CHUNK; ++j) {
            float i_t = pin[j * 32 + lane];
            // exact reference association order — do not reassociate
            float dv = (0.04f * v * v + 5.0f * v + 140.0f - u + i_t) * 0.5f;
            float du = (0.02f * (0.2f * v - u)) * 0.5f;
            v = v + dv;
            u = u + du;
            bool  fired = (v >= 30.0f);
            float s = fired ? 1.0f : 0.0f;
            v = fired ? -65.0f : v;
            u = fired ? u + 8.0f : u;
            po[              j * 32 + lane] = s;
            po[CHUNK * 32  + j * 32 + lane] = v;
            po[2*CHUNK*32  + j * 32 + lane] = u;
        }
        __syncwarp();

        if (lane == 0) {
            FENCE_ASYNC();   // order the STS above before async-proxy reads
            const uint32_t so = sb + SM_OUT + slot_out * 3 * CHUNKB;
            const int      ty = k * CHUNK;
            TMA_STORE(&m_s, n0, ty, b, so);
            TMA_STORE(&m_v, n0, ty, b, so + CHUNKB);
            TMA_STORE(&m_u, n0, ty, b, so + 2 * CHUNKB);
            TMA_COMMIT();

            const int kn = k + IN_RING;
            if (kn < NCHUNK) {   // refill the slot we just consumed
                MBAR_EXPECT_TX(sb + SM_MBAR + slot_in * 8, CHUNKB);
                TMA_LOAD(sb + SM_IN + slot_in * CHUNKB, &m_in, n0, kn * CHUNK, b,
                         sb + SM_MBAR + slot_in * 8);
            }
        }

        if (++slot_in == IN_RING) { slot_in = 0; phase_in ^= 1; }
        if (++slot_out == OUT_RING) slot_out = 0;
    }

    if (lane == 0) TMA_WAIT(0);   // drain outstanding stores before exit
}

// ---------------- fallback (no driver entry point): round-2 style ----------------
__global__ __launch_bounds__(32, 8)
void izh_fallback_kernel(const float* __restrict__ in,
                         float* __restrict__ out_s,
                         float* __restrict__ out_v,
                         float* __restrict__ out_u)
{
    int tid = blockIdx.x * 32 + threadIdx.x;
    int b   = tid >> 9;
    int n   = tid & 511;
    const float* __restrict__ ip = in    + b * PLANE + n;
    float* __restrict__ sp       = out_s + b * PLANE + n;
    float* __restrict__ vp       = out_v + b * PLANE + n;
    float* __restrict__ up       = out_u + b * PLANE + n;

    float v = -65.0f, u = -13.0f;
    float cur[16];
    #pragma unroll
    for (int j = 0; j < 16; ++j) cur[j] = __ldcs(ip + j * NNEUR);
    ip += 16 * NNEUR;

    #pragma unroll 1
    for (int c = 0; c < (NSTEPS / 16) - 1; ++c) {
        float nxt[16];
        #pragma unroll
        for (int j = 0; j < 16; ++j) nxt[j] = __ldcs(ip + j * NNEUR);
        ip += 16 * NNEUR;
        #pragma unroll
        for (int j = 0; j < 16; ++j) {
            float i_t = cur[j];
            float dv = (0.04f * v * v + 5.0f * v + 140.0f - u + i_t) * 0.5f;
            float du = (0.02f * (0.2f * v - u)) * 0.5f;
            v = v + dv; u = u + du;
            bool fired = (v >= 30.0f);
            float s = fired ? 1.0f : 0.0f;
            v = fired ? -65.0f : v;
            u = fired ? u + 8.0f : u;
            __stcs(sp + j * NNEUR, s);
            __stcs(vp + j * NNEUR, v);
            __stcs(up + j * NNEUR, u);
        }
        sp += 16 * NNEUR; vp += 16 * NNEUR; up += 16 * NNEUR;
        #pragma unroll
        for (int j = 0; j < 16; ++j) cur[j] = nxt[j];
    }
    #pragma unroll
    for (int j = 0; j < 16; ++j) {
        float i_t = cur[j];
        float dv = (0.04f * v * v + 5.0f * v + 140.0f - u + i_t) * 0.5f;
        float du = (0.02f * (0.2f * v - u)) * 0.5f;
        v = v + dv; u = u + du;
        bool fired = (v >= 30.0f);
        float s = fired ? 1.0f : 0.0f;
        v = fired ? -65.0f : v;
        u = fired ? u + 8.0f : u;
        __stcs(sp + j * NNEUR, s);
        __stcs(vp + j * NNEUR, v);
        __stcs(up + j * NNEUR, u);
    }
}

// ---------------- host ----------------
typedef CUresult (*tmap_encode_fn)(
    CUtensorMap*, CUtensorMapDataType, cuuint32_t, void*,
    const cuuint64_t*, const cuuint64_t*, const cuuint32_t*, const cuuint32_t*,
    CUtensorMapInterleave, CUtensorMapSwizzle, CUtensorMapL2promotion,
    CUtensorMapFloatOOBfill);

static bool make_map(tmap_encode_fn fn, CUtensorMap* m, void* base)
{
    cuuint64_t dims[3]    = { NNEUR, NSTEPS, BATCH };
    cuuint64_t strides[2] = { (cuuint64_t)NNEUR * 4,
                              (cuuint64_t)NSTEPS * NNEUR * 4 };
    cuuint32_t box[3]     = { 32, CHUNK, 1 };
    cuuint32_t es[3]      = { 1, 1, 1 };
    return fn(m, CU_TENSOR_MAP_DATA_TYPE_FLOAT32, 3, base,
              dims, strides, box, es,
              CU_TENSOR_MAP_INTERLEAVE_NONE, CU_TENSOR_MAP_SWIZZLE_NONE,
              CU_TENSOR_MAP_L2_PROMOTION_L2_128B,
              CU_TENSOR_MAP_FLOAT_OOB_FILL_NONE) == CUDA_SUCCESS;
}

extern "C" void kernel_launch(void* const* d_in, const int* in_sizes, int n_in,
                              void* d_out, int out_size)
{
    float* in  = (float*)d_in[0];
    float* out = (float*)d_out;

    void* p = nullptr;
    cudaDriverEntryPointQueryResult qr = cudaDriverEntryPointSuccess;
    cudaGetDriverEntryPointByVersion("cuTensorMapEncodeTiled", &p, 12000,
                                     cudaEnableDefault, &qr);
    if (p) {
        CUtensorMap m_in, m_s, m_v, m_u;
        tmap_encode_fn fn = (tmap_encode_fn)p;
        bool ok = make_map(fn, &m_in, in)
               && make_map(fn, &m_s,  out)
               && make_map(fn, &m_v,  out + NTOT)
               && make_map(fn, &m_u,  out + 2 * NTOT);
        if (ok) {
            cudaFuncSetAttribute(izh_tma_kernel,
                                 cudaFuncAttributeMaxDynamicSharedMemorySize,
                                 SM_TOTAL);
            izh_tma_kernel<<<512, 32, SM_TOTAL>>>(m_in, m_s, m_v, m_u);
            return;
        }
    }
    izh_fallback_kernel<<<512, 32>>>(in, out, out + NTOT, out + 2 * NTOT);
}

// round 11
// speedup vs baseline: 1.3595x; 1.0192x over previous
#include <cuda_runtime.h>
#include <cuda.h>
#include <cstdint>

// Izhikevich neuron simulation on GB300 — round 6: TMA-driven pipeline.
// input:  [32, 2000, 512] fp32; output: concat(s, v, u), each [32, 2000, 512].
//
// 512 CTAs x 32 threads. Each CTA owns 32 consecutive neurons of one batch.
// TMA (cp.async.bulk.tensor.3d) moves all data:
//   - input: 6-deep SMEM ring, lane0 issues loads, mbarrier per slot
//   - compute: all 32 lanes, serial 2000-step chain, SMEM -> SMEM
//   - output: 3-deep SMEM ring x 3 streams, lane0 issues TMA stores,
//             bulk_group wait guards slot reuse
// No LDG/STG in the hot path; the warp only pays compute + a few TMA issues.

#define BATCH    32
#define NSTEPS   2000
#define NNEUR    512
#define PLANE    (NSTEPS * NNEUR)
#define NTOT     (BATCH * PLANE)
#define CHUNK    25
#define NCHUNK   (NSTEPS / CHUNK)     // 80
#define IN_RING  6
#define OUT_RING 3
#define ROWB     128                  // 32 floats per row
#define CHUNKB   (CHUNK * ROWB)       // 3200 bytes per chunk per stream

// SMEM layout (bytes)
#define SM_MBAR  0                    // IN_RING * 8
#define SM_IN    128
#define SM_OUT   (SM_IN + IN_RING * CHUNKB)
#define SM_TOTAL (SM_OUT + 3 * OUT_RING * CHUNKB)   // 48128 B

// ---------------- PTX helpers ----------------
__device__ __forceinline__ uint32_t smem_u32(const void* p) {
    uint32_t a;
    asm("{ .reg .u64 t; cvta.to.shared.u64 t, %1; cvt.u32.u64 %0, t; }"
        : "=r"(a) : "l"(p));
    return a;
}
#define MBAR_INIT(addr, cnt) \
    asm volatile("mbarrier.init.shared.b64 [%0], %1;" :: "r"(addr), "r"(cnt) : "memory")
#define MBAR_EXPECT_TX(addr, bytes) \
    asm volatile("mbarrier.arrive.expect_tx.shared.b64 _, [%0], %1;" \
                 :: "r"(addr), "r"(bytes) : "memory")
#define MBAR_WAIT(addr, parity) do {                                         \
    asm volatile(                                                            \
        "{\n\t.reg .pred P;\n\t"                                             \
        "W_%=:\n\t"                                                          \
        "mbarrier.try_wait.parity.acquire.cta.shared::cta.b64 P, [%0], %1, 0x989680;\n\t" \
        "@P bra.uni D_%=;\n\t"                                               \
        "bra.uni W_%=;\n\t"                                                  \
        "D_%=:\n\t}"                                                         \
        :: "r"(addr), "r"(parity) : "memory");                               \
} while (0)
#define TMA_LOAD(smem, map, cx, cy, cz, mbar) \
    asm volatile("cp.async.bulk.tensor.3d.shared::cta.global.tile.mbarrier::complete_tx::bytes " \
                 "[%0], [%1, {%2, %3, %4}], [%5];" \
                 :: "r"(smem), "l"(map), "r"(cx), "r"(cy), "r"(cz), "r"(mbar) : "memory")
#define TMA_STORE(map, cx, cy, cz, smem) \
    asm volatile("cp.async.bulk.tensor.3d.global.shared::cta.tile.bulk_group " \
                 "[%0, {%1, %2, %3}], [%4];" \
                 :: "l"(map), "r"(cx), "r"(cy), "r"(cz), "r"(smem) : "memory")
#define TMA_COMMIT()      asm volatile("cp.async.bulk.commit_group;" ::: "memory")
#define TMA_WAIT(n)       asm volatile("cp.async.bulk.wait_group.read %0;" :: "n"(n) : "memory")
#define FENCE_ASYNC()     asm volatile("fence.proxy.async.shared::cta;" ::: "memory")

// ---------------- TMA kernel ----------------
__global__ __launch_bounds__(32)
void izh_tma_kernel(const __grid_constant__ CUtensorMap m_in,
                    const __grid_constant__ CUtensorMap m_s,
                    const __grid_constant__ CUtensorMap m_v,
                    const __grid_constant__ CUtensorMap m_u)
{
    extern __shared__ char smem[];
    const uint32_t sb   = smem_u32(smem);
    const int      lane = threadIdx.x;
    const int      bid  = blockIdx.x;
    const int      b    = bid >> 4;          // batch
    const int      n0   = (bid & 15) * 32;   // first neuron

    if (lane == 0) {
        #pragma unroll
        for (int s = 0; s < IN_RING; ++s)
            MBAR_INIT(sb + SM_MBAR + s * 8, 1);
    }
    __syncwarp();
    if (lane == 0) {
        // prologue: fill the whole input ring
        #pragma unroll
        for (int s = 0; s < IN_RING; ++s) {
            MBAR_EXPECT_TX(sb + SM_MBAR + s * 8, CHUNKB);
            TMA_LOAD(sb + SM_IN + s * CHUNKB, &m_in, n0, s * CHUNK, b,
                     sb + SM_MBAR + s * 8);
        }
    }

    float v = -65.0f;
    float u = -13.0f;   // B * C

    int slot_in = 0, phase_in = 0, slot_out = 0;

    #pragma unroll 1
    for (int k = 0; k < NCHUNK; ++k) {
        // input chunk k ready?
        MBAR_WAIT(sb + SM_MBAR + slot_in * 8, phase_in);
        // output slot free? (group from chunk k-3 retired)
        if (lane == 0) TMA_WAIT(OUT_RING - 1);
        __syncwarp();

        const float* __restrict__ pin =
            (const float*)(smem + SM_IN + slot_in * CHUNKB);
        float* __restrict__ po =
            (float*)(smem + SM_OUT + slot_out * 3 * CHUNKB);

        #pragma unroll
        for (int j = 0; j < CHUNK; ++j) {
            float i_t = pin[j * 32 + lane];
            // exact reference association order — do not reassociate
            float dv = (0.04f * v * v + 5.0f * v + 140.0f - u + i_t) * 0.5f;
            float du = (0.02f * (0.2f * v - u)) * 0.5f;
            v = v + dv;
            u = u + du;
            bool  fired = (v >= 30.0f);
            float s = fired ? 1.0f : 0.0f;
            v = fired ? -65.0f : v;
            u = fired ? u + 8.0f : u;
            po[              j * 32 + lane] = s;
            po[CHUNK * 32  + j * 32 + lane] = v;
            po[2*CHUNK*32  + j * 32 + lane] = u;
        }
        __syncwarp();

        if (lane == 0) {
            FENCE_ASYNC();   // order the STS above before async-proxy reads
            const uint32_t so = sb + SM_OUT + slot_out * 3 * CHUNKB;
            const int      ty = k * CHUNK;
            TMA_STORE(&m_s, n0, ty, b, so);
            TMA_STORE(&m_v, n0, ty, b, so + CHUNKB);
            TMA_STORE(&m_u, n0, ty, b, so + 2 * CHUNKB);
            TMA_COMMIT();

            const int kn = k + IN_RING;
            if (kn < NCHUNK) {   // refill the slot we just consumed
                MBAR_EXPECT_TX(sb + SM_MBAR + slot_in * 8, CHUNKB);
                TMA_LOAD(sb + SM_IN + slot_in * CHUNKB, &m_in, n0, kn * CHUNK, b,
                         sb + SM_MBAR + slot_in * 8);
            }
        }

        if (++slot_in == IN_RING) { slot_in = 0; phase_in ^= 1; }
        if (++slot_out == OUT_RING) slot_out = 0;
    }

    if (lane == 0) TMA_WAIT(0);   // drain outstanding stores before exit
}

// ---------------- fallback (no driver entry point): round-2 style ----------------
__global__ __launch_bounds__(32, 8)
void izh_fallback_kernel(const float* __restrict__ in,
                         float* __restrict__ out_s,
                         float* __restrict__ out_v,
                         float* __restrict__ out_u)
{
    int tid = blockIdx.x * 32 + threadIdx.x;
    int b   = tid >> 9;
    int n   = tid & 511;
    const float* __restrict__ ip = in    + b * PLANE + n;
    float* __restrict__ sp       = out_s + b * PLANE + n;
    float* __restrict__ vp       = out_v + b * PLANE + n;
    float* __restrict__ up       = out_u + b * PLANE + n;

    float v = -65.0f, u = -13.0f;
    float cur[16];
    #pragma unroll
    for (int j = 0; j < 16; ++j) cur[j] = __ldcs(ip + j * NNEUR);
    ip += 16 * NNEUR;

    #pragma unroll 1
    for (int c = 0; c < (NSTEPS / 16) - 1; ++c) {
        float nxt[16];
        #pragma unroll
        for (int j = 0; j < 16; ++j) nxt[j] = __ldcs(ip + j * NNEUR);
        ip += 16 * NNEUR;
        #pragma unroll
        for (int j = 0; j < 16; ++j) {
            float i_t = cur[j];
            float dv = (0.04f * v * v + 5.0f * v + 140.0f - u + i_t) * 0.5f;
            float du = (0.02f * (0.2f * v - u)) * 0.5f;
            v = v + dv; u = u + du;
            bool fired = (v >= 30.0f);
            float s = fired ? 1.0f : 0.0f;
            v = fired ? -65.0f : v;
            u = fired ? u + 8.0f : u;
            __stcs(sp + j * NNEUR, s);
            __stcs(vp + j * NNEUR, v);
            __stcs(up + j * NNEUR, u);
        }
        sp += 16 * NNEUR; vp += 16 * NNEUR; up += 16 * NNEUR;
        #pragma unroll
        for (int j = 0; j < 16; ++j) cur[j] = nxt[j];
    }
    #pragma unroll
    for (int j = 0; j < 16; ++j) {
        float i_t = cur[j];
        float dv = (0.04f * v * v + 5.0f * v + 140.0f - u + i_t) * 0.5f;
        float du = (0.02f * (0.2f * v - u)) * 0.5f;
        v = v + dv; u = u + du;
        bool fired = (v >= 30.0f);
        float s = fired ? 1.0f : 0.0f;
        v = fired ? -65.0f : v;
        u = fired ? u + 8.0f : u;
        __stcs(sp + j * NNEUR, s);
        __stcs(vp + j * NNEUR, v);
        __stcs(up + j * NNEUR, u);
    }
}

// ---------------- host ----------------
typedef CUresult (*tmap_encode_fn)(
    CUtensorMap*, CUtensorMapDataType, cuuint32_t, void*,
    const cuuint64_t*, const cuuint64_t*, const cuuint32_t*, const cuuint32_t*,
    CUtensorMapInterleave, CUtensorMapSwizzle, CUtensorMapL2promotion,
    CUtensorMapFloatOOBfill);

static bool make_map(tmap_encode_fn fn, CUtensorMap* m, void* base)
{
    cuuint64_t dims[3]    = { NNEUR, NSTEPS, BATCH };
    cuuint64_t strides[2] = { (cuuint64_t)NNEUR * 4,
                              (cuuint64_t)NSTEPS * NNEUR * 4 };
    cuuint32_t box[3]     = { 32, CHUNK, 1 };
    cuuint32_t es[3]      = { 1, 1, 1 };
    return fn(m, CU_TENSOR_MAP_DATA_TYPE_FLOAT32, 3, base,
              dims, strides, box, es,
              CU_TENSOR_MAP_INTERLEAVE_NONE, CU_TENSOR_MAP_SWIZZLE_NONE,
              CU_TENSOR_MAP_L2_PROMOTION_L2_128B,
              CU_TENSOR_MAP_FLOAT_OOB_FILL_NONE) == CUDA_SUCCESS;
}

extern "C" void kernel_launch(void* const* d_in, const int* in_sizes, int n_in,
                              void* d_out, int out_size)
{
    float* in  = (float*)d_in[0];
    float* out = (float*)d_out;

    void* p = nullptr;
    cudaDriverEntryPointQueryResult qr = cudaDriverEntryPointSuccess;
    cudaGetDriverEntryPointByVersion("cuTensorMapEncodeTiled", &p, 12000,
                                     cudaEnableDefault, &qr);
    if (p) {
        CUtensorMap m_in, m_s, m_v, m_u;
        tmap_encode_fn fn = (tmap_encode_fn)p;
        bool ok = make_map(fn, &m_in, in)
               && make_map(fn, &m_s,  out)
               && make_map(fn, &m_v,  out + NTOT)
               && make_map(fn, &m_u,  out + 2 * NTOT);
        if (ok) {
            cudaFuncSetAttribute(izh_tma_kernel,
                                 cudaFuncAttributeMaxDynamicSharedMemorySize,
                                 SM_TOTAL);
            izh_tma_kernel<<<512, 32, SM_TOTAL>>>(m_in, m_s, m_v, m_u);
            return;
        }
    }
    izh_fallback_kernel<<<512, 32>>>(in, out, out + NTOT, out + 2 * NTOT);
}

// round 12
// speedup vs baseline: 1.5683x; 1.1535x over previous
#include <cuda_runtime.h>
#include <cuda.h>
#include <cstdint>

// Izhikevich neuron simulation on GB300 — round 7: wide-CTA TMA pipeline.
// input:  [32, 2000, 512] fp32; output: concat(s, v, u), each [32, 2000, 512].
//
// 128 CTAs x 128 threads. Each CTA owns 128 consecutive neurons of one batch
// (4 warps x 32 lanes). TMA boxes are 128 neurons wide = 512B contiguous per
// timestep row (4x better DRAM/L2 write locality than round 6's 128B), and
// <=1 CTA per SM kills the 3-vs-4-CTA imbalance tail.
//   - input: 6-deep SMEM ring (one mbarrier per slot), thread0 issues loads
//   - compute: all 128 threads, serial 2000-step chain, SMEM -> SMEM
//   - output: 3-deep ring x 3 streams, thread0 TMA stores, bulk_group guards

#define BATCH    32
#define NSTEPS   2000
#define NNEUR    512
#define PLANE    (NSTEPS * NNEUR)
#define NTOT     (BATCH * PLANE)
#define NWIDE    128                  // neurons per CTA
#define CHUNK    25
#define NCHUNK   (NSTEPS / CHUNK)     // 80
#define IN_RING  6
#define OUT_RING 3
#define ROWB     (NWIDE * 4)          // 512 bytes per timestep row
#define CHUNKB   (CHUNK * ROWB)       // 12800 bytes per chunk per stream

// SMEM layout (bytes)
#define SM_MBAR  0                    // IN_RING * 8
#define SM_IN    128
#define SM_OUT   (SM_IN + IN_RING * CHUNKB)
#define SM_TOTAL (SM_OUT + 3 * OUT_RING * CHUNKB)   // 192,128 B

// ---------------- PTX helpers ----------------
__device__ __forceinline__ uint32_t smem_u32(const void* p) {
    uint32_t a;
    asm("{ .reg .u64 t; cvta.to.shared.u64 t, %1; cvt.u32.u64 %0, t; }"
        : "=r"(a) : "l"(p));
    return a;
}
#define MBAR_INIT(addr, cnt) \
    asm volatile("mbarrier.init.shared.b64 [%0], %1;" :: "r"(addr), "r"(cnt) : "memory")
#define MBAR_EXPECT_TX(addr, bytes) \
    asm volatile("mbarrier.arrive.expect_tx.shared.b64 _, [%0], %1;" \
                 :: "r"(addr), "r"(bytes) : "memory")
#define MBAR_WAIT(addr, parity) do {                                         \
    asm volatile(                                                            \
        "{\n\t.reg .pred P;\n\t"                                             \
        "W_%=:\n\t"                                                          \
        "mbarrier.try_wait.parity.acquire.cta.shared::cta.b64 P, [%0], %1, 0x989680;\n\t" \
        "@P bra.uni D_%=;\n\t"                                               \
        "bra.uni W_%=;\n\t"                                                  \
        "D_%=:\n\t}"                                                         \
        :: "r"(addr), "r"(parity) : "memory");                               \
} while (0)
#define TMA_LOAD(smem, map, cx, cy, cz, mbar) \
    asm volatile("cp.async.bulk.tensor.3d.shared::cta.global.tile.mbarrier::complete_tx::bytes " \
                 "[%0], [%1, {%2, %3, %4}], [%5];" \
                 :: "r"(smem), "l"(map), "r"(cx), "r"(cy), "r"(cz), "r"(mbar) : "memory")
#define TMA_STORE(map, cx, cy, cz, smem) \
    asm volatile("cp.async.bulk.tensor.3d.global.shared::cta.tile.bulk_group " \
                 "[%0, {%1, %2, %3}], [%4];" \
                 :: "l"(map), "r"(cx), "r"(cy), "r"(cz), "r"(smem) : "memory")
#define TMA_COMMIT()      asm volatile("cp.async.bulk.commit_group;" ::: "memory")
#define TMA_WAIT(n)       asm volatile("cp.async.bulk.wait_group.read %0;" :: "n"(n) : "memory")
#define FENCE_ASYNC()     asm volatile("fence.proxy.async.shared::cta;" ::: "memory")

// ---------------- TMA kernel ----------------
__global__ __launch_bounds__(128, 1)
void izh_tma_kernel(const __grid_constant__ CUtensorMap m_in,
                    const __grid_constant__ CUtensorMap m_s,
                    const __grid_constant__ CUtensorMap m_v,
                    const __grid_constant__ CUtensorMap m_u)
{
    extern __shared__ char smem[];
    const uint32_t sb  = smem_u32(smem);
    const int      tx  = threadIdx.x;            // 0..127
    const int      bid = blockIdx.x;             // 0..127
    const int      b   = bid >> 2;               // batch
    const int      n0  = (bid & 3) * NWIDE;      // first neuron of tile

    if (tx == 0) {
        #pragma unroll
        for (int s = 0; s < IN_RING; ++s)
            MBAR_INIT(sb + SM_MBAR + s * 8, 1);
    }
    __syncthreads();                              // mbarriers visible
    if (tx == 0) {
        // prologue: fill the whole input ring
        #pragma unroll
        for (int s = 0; s < IN_RING; ++s) {
            MBAR_EXPECT_TX(sb + SM_MBAR + s * 8, CHUNKB);
            TMA_LOAD(sb + SM_IN + s * CHUNKB, &m_in, n0, s * CHUNK, b,
                     sb + SM_MBAR + s * 8);
        }
    }

    float v = -65.0f;
    float u = -13.0f;   // B * C

    int slot_in = 0, phase_in = 0, slot_out = 0;

    #pragma unroll 1
    for (int k = 0; k < NCHUNK; ++k) {
        // input chunk k ready? (all threads wait; acquire orders the LDS below)
        MBAR_WAIT(sb + SM_MBAR + slot_in * 8, phase_in);
        // output slot free? group from chunk k-3 has had its SMEM read out.
        if (tx == 0) TMA_WAIT(OUT_RING - 1);
        __syncthreads();

        const float* __restrict__ pin =
            (const float*)(smem + SM_IN + slot_in * CHUNKB);
        float* __restrict__ po =
            (float*)(smem + SM_OUT + slot_out * 3 * CHUNKB);

        #pragma unroll
        for (int j = 0; j < CHUNK; ++j) {
            float i_t = pin[j * NWIDE + tx];
            // exact reference association order — do not reassociate
            float dv = (0.04f * v * v + 5.0f * v + 140.0f - u + i_t) * 0.5f;
            float du = (0.02f * (0.2f * v - u)) * 0.5f;
            v = v + dv;
            u = u + du;
            bool  fired = (v >= 30.0f);
            float s = fired ? 1.0f : 0.0f;
            v = fired ? -65.0f : v;
            u = fired ? u + 8.0f : u;
            po[                   j * NWIDE + tx] = s;
            po[    CHUNK * NWIDE + j * NWIDE + tx] = v;
            po[2 * CHUNK * NWIDE + j * NWIDE + tx] = u;
        }
        __syncthreads();                          // all STS done

        if (tx == 0) {
            FENCE_ASYNC();   // order generic-proxy STS before async-proxy reads
            const uint32_t so = sb + SM_OUT + slot_out * 3 * CHUNKB;
            const int      ty = k * CHUNK;
            TMA_STORE(&m_s, n0, ty, b, so);
            TMA_STORE(&m_v, n0, ty, b, so + CHUNKB);
            TMA_STORE(&m_u, n0, ty, b, so + 2 * CHUNKB);
            TMA_COMMIT();

            const int kn = k + IN_RING;
            if (kn < NCHUNK) {   // refill the input slot we just consumed
                MBAR_EXPECT_TX(sb + SM_MBAR + slot_in * 8, CHUNKB);
                TMA_LOAD(sb + SM_IN + slot_in * CHUNKB, &m_in, n0, kn * CHUNK, b,
                         sb + SM_MBAR + slot_in * 8);
            }
        }

        if (++slot_in == IN_RING) { slot_in = 0; phase_in ^= 1; }
        if (++slot_out == OUT_RING) slot_out = 0;
    }

    if (tx == 0) TMA_WAIT(0);   // drain outstanding store groups before exit
}

// ---------------- fallback (no driver entry point): round-2 style ----------------
__global__ __launch_bounds__(32, 8)
void izh_fallback_kernel(const float* __restrict__ in,
                         float* __restrict__ out_s,
                         float* __restrict__ out_v,
                         float* __restrict__ out_u)
{
    int tid = blockIdx.x * 32 + threadIdx.x;
    int b   = tid >> 9;
    int n   = tid & 511;
    const float* __restrict__ ip = in    + b * PLANE + n;
    float* __restrict__ sp       = out_s + b * PLANE + n;
    float* __restrict__ vp       = out_v + b * PLANE + n;
    float* __restrict__ up       = out_u + b * PLANE + n;

    float v = -65.0f, u = -13.0f;
    float cur[16];
    #pragma unroll
    for (int j = 0; j < 16; ++j) cur[j] = __ldcs(ip + j * NNEUR);
    ip += 16 * NNEUR;

    #pragma unroll 1
    for (int c = 0; c < (NSTEPS / 16) - 1; ++c) {
        float nxt[16];
        #pragma unroll
        for (int j = 0; j < 16; ++j) nxt[j] = __ldcs(ip + j * NNEUR);
        ip += 16 * NNEUR;
        #pragma unroll
        for (int j = 0; j < 16; ++j) {
            float i_t = cur[j];
            float dv = (0.04f * v * v + 5.0f * v + 140.0f - u + i_t) * 0.5f;
            float du = (0.02f * (0.2f * v - u)) * 0.5f;
            v = v + dv; u = u + du;
            bool fired = (v >= 30.0f);
            float s = fired ? 1.0f : 0.0f;
            v = fired ? -65.0f : v;
            u = fired ? u + 8.0f : u;
            __stcs(sp + j * NNEUR, s);
            __stcs(vp + j * NNEUR, v);
            __stcs(up + j * NNEUR, u);
        }
        sp += 16 * NNEUR; vp += 16 * NNEUR; up += 16 * NNEUR;
        #pragma unroll
        for (int j = 0; j < 16; ++j) cur[j] = nxt[j];
    }
    #pragma unroll
    for (int j = 0; j < 16; ++j) {
        float i_t = cur[j];
        float dv = (0.04f * v * v + 5.0f * v + 140.0f - u + i_t) * 0.5f;
        float du = (0.02f * (0.2f * v - u)) * 0.5f;
        v = v + dv; u = u + du;
        bool fired = (v >= 30.0f);
        float s = fired ? 1.0f : 0.0f;
        v = fired ? -65.0f : v;
        u = fired ? u + 8.0f : u;
        __stcs(sp + j * NNEUR, s);
        __stcs(vp + j * NNEUR, v);
        __stcs(up + j * NNEUR, u);
    }
}

// ---------------- host ----------------
typedef CUresult (*tmap_encode_fn)(
    CUtensorMap*, CUtensorMapDataType, cuuint32_t, void*,
    const cuuint64_t*, const cuuint64_t*, const cuuint32_t*, const cuuint32_t*,
    CUtensorMapInterleave, CUtensorMapSwizzle, CUtensorMapL2promotion,
    CUtensorMapFloatOOBfill);

static bool make_map(tmap_encode_fn fn, CUtensorMap* m, void* base,
                     CUtensorMapL2promotion promo)
{
    cuuint64_t dims[3]    = { NNEUR, NSTEPS, BATCH };
    cuuint64_t strides[2] = { (cuuint64_t)NNEUR * 4,
                              (cuuint64_t)NSTEPS * NNEUR * 4 };
    cuuint32_t box[3]     = { NWIDE, CHUNK, 1 };
    cuuint32_t es[3]      = { 1, 1, 1 };
    return fn(m, CU_TENSOR_MAP_DATA_TYPE_FLOAT32, 3, base,
              dims, strides, box, es,
              CU_TENSOR_MAP_INTERLEAVE_NONE, CU_TENSOR_MAP_SWIZZLE_NONE,
              promo,
              CU_TENSOR_MAP_FLOAT_OOB_FILL_NONE) == CUDA_SUCCESS;
}

extern "C" void kernel_launch(void* const* d_in, const int* in_sizes, int n_in,
                              void* d_out, int out_size)
{
    float* in  = (float*)d_in[0];
    float* out = (float*)d_out;

    void* p = nullptr;
    cudaDriverEntryPointQueryResult qr = cudaDriverEntryPointSuccess;
    cudaGetDriverEntryPointByVersion("cuTensorMapEncodeTiled", &p, 12000,
                                     cudaEnableDefault, &qr);
    if (p) {
        CUtensorMap m_in, m_s, m_v, m_u;
        tmap_encode_fn fn = (tmap_encode_fn)p;
        bool ok = make_map(fn, &m_in, in,          CU_TENSOR_MAP_L2_PROMOTION_L2_256B)
               && make_map(fn, &m_s,  out,         CU_TENSOR_MAP_L2_PROMOTION_L2_128B)
               && make_map(fn, &m_v,  out + NTOT,  CU_TENSOR_MAP_L2_PROMOTION_L2_128B)
               && make_map(fn, &m_u,  out + 2*NTOT, CU_TENSOR_MAP_L2_PROMOTION_L2_128B);
        if (ok) {
            cudaFuncSetAttribute(izh_tma_kernel,
                                 cudaFuncAttributeMaxDynamicSharedMemorySize,
                                 SM_TOTAL);
            izh_tma_kernel<<<128, 128, SM_TOTAL>>>(m_in, m_s, m_v, m_u);
            return;
        }
    }
    izh_fallback_kernel<<<512, 32>>>(in, out, out + NTOT, out + 2 * NTOT);
}